// round 10
// baseline (speedup 1.0000x reference)
#include <cuda_runtime.h>
#include <cuda_bf16.h>

// Problem constants (fixed by the dataset reference)
#define Bq   64
#define Sq   131072
#define SqV  (Sq / 4)
#define WIN  100

#define CHUNK 8192
#define HALO  128                 // halo elements each side (multiple of 32)
#define EXT   (CHUNK + 2*HALO)    // 8448
#define TPB   256
#define CPR   (Sq / CHUNK)        // 16 chunks per row
#define NBLK  (Bq * CPR)          // 1024 blocks, 7 CTAs/SM -> ~one wave
#define GRP   (CHUNK / 4 / TPB)   // 8 stages of 1024 elements

#define EXTW  (EXT / 32)          // 264 bitmap words
#define GUARD 4
#define PADW  (EXTW + 2*GUARD)    // 272

__device__ float4       g_part[NBLK];
__device__ unsigned int g_done;

__device__ __forceinline__ float fex2(float x) {
    float r; asm("ex2.approx.ftz.f32 %0, %1;" : "=f"(r) : "f"(x)); return r;
}
__device__ __forceinline__ float flg2(float x) {
    float r; asm("lg2.approx.ftz.f32 %0, %1;" : "=f"(r) : "f"(x)); return r;
}
__device__ __forceinline__ float frcp(float x) {
    float r; asm("rcp.approx.ftz.f32 %0, %1;" : "=f"(r) : "f"(x)); return r;
}
__device__ __forceinline__ void cp16(unsigned dst, const void* src) {
    asm volatile("cp.async.cg.shared.global [%0], [%1], 16;" :: "r"(dst), "l"(src));
}

__device__ __forceinline__ void elem(float x0, float x1, float x2,
                                     int t, unsigned m,
                                     float a0, float a1, float a2,
                                     float& sa, float& sm)
{
    const float L2E = 1.44269504088896340736f;
    float xt  = (t == 0) ? x0 : ((t == 1) ? x1 : x2);
    float xa  = (t == 0) ? x1 : x0;
    float xb  = (t <  2) ? x2 : x1;
    float aw  = (t == 0) ? a0 : ((t == 1) ? a1 : a2);
    float nxt = -xt * L2E;
    float ea  = fex2(__fmaf_rn(xa, L2E, nxt));
    float eb  = fex2(__fmaf_rn(xb, L2E, nxt));
    float q   = 1.f + ea + eb;            // = softmax_sum / e_t
    float ce2 = flg2(q);                  // ln2 folded into aw
    float p   = frcp(q);
    float omp = 1.f - p;
    float f   = aw * (omp * omp) * ce2;
    sa += f;
    if (m) sm += f;
}

__global__ __launch_bounds__(TPB, 7)
void focal_main(const float* __restrict__ inputs,
                const int*   __restrict__ targets,
                const float* __restrict__ alpha,
                float*       __restrict__ out)
{
    __shared__ float4   sStage[2][TPB * 3];     // 24 KB staging ring
    __shared__ unsigned sPos[PADW];             // positive-flag bitmap (+guards)
    __shared__ unsigned sMsk[PADW];             // window-mask bitmap
    __shared__ unsigned sCls2[CHUNK / 16];      // 2-bit classes, 2 KB
    __shared__ float rA[TPB / 32], rB[TPB / 32], rC[TPB / 32];
    __shared__ int   rH[TPB / 32];
    __shared__ float sRS[Bq], sRC[Bq];
    __shared__ bool  sLast;

    const int row        = blockIdx.y;
    const int chunk      = blockIdx.x;
    const int chunkStart = chunk * CHUNK;
    const int tid        = threadIdx.x;
    const int lane       = tid & 31, warp = tid >> 5;

    const float4* in4 = reinterpret_cast<const float4*>(
        inputs + ((size_t)row * Sq + (size_t)chunkStart) * 3);

    // ---- Kick off stages 0 and 1 immediately (overlaps whole preamble).
    const unsigned sb0 = (unsigned)__cvta_generic_to_shared(&sStage[0][tid * 3]);
    const unsigned sb1 = (unsigned)__cvta_generic_to_shared(&sStage[1][tid * 3]);
    {
        const float4* s0 = in4 + tid * 3;
        cp16(sb0,      s0);  cp16(sb0 + 16, s0 + 1);  cp16(sb0 + 32, s0 + 2);
        asm volatile("cp.async.commit_group;" ::: "memory");
        const float4* s1 = in4 + TPB * 3 + tid * 3;
        cp16(sb1,      s1);  cp16(sb1 + 16, s1 + 1);  cp16(sb1 + 32, s1 + 2);
        asm volatile("cp.async.commit_group;" ::: "memory");
    }

    // ---- Zero bitmap guards.
    if (tid < GUARD) { sPos[tid] = 0; sPos[PADW - 1 - tid] = 0; }

    // ---- Targets: int4 loads -> pos bitmap (shfl-merged) + 2-bit class words.
    const int4* tgt4     = reinterpret_cast<const int4*>(targets);
    const int   rowVecLo = row * SqV;
    const int   baseVec  = rowVecLo + (chunkStart - HALO) / 4;

    #pragma unroll 1
    for (int it = 0; it < 9; it++) {                 // 9*256 covers 2112 (tail 64)
        if (it == 8 && warp >= 2) break;
        const int vecIdx = it * TPB + tid;
        const int gv     = baseVec + vecIdx;
        const int gvc    = min(max(gv, rowVecLo), rowVecLo + SqV - 1);
        int4 v = __ldg(tgt4 + gvc);
        const bool valid = (unsigned)(gv - rowVecLo) < (unsigned)SqV;

        unsigned nib = (v.x > 0 ? 1u : 0u) | (v.y > 0 ? 2u : 0u)
                     | (v.z > 0 ? 4u : 0u) | (v.w > 0 ? 8u : 0u);
        if (!valid) nib = 0;

        unsigned wv = nib << ((lane & 7) * 4);
        wv |= __shfl_xor_sync(0xffffffffu, wv, 1);
        wv |= __shfl_xor_sync(0xffffffffu, wv, 2);
        wv |= __shfl_xor_sync(0xffffffffu, wv, 4);
        if ((lane & 7) == 0) sPos[GUARD + (vecIdx >> 3)] = wv;

        // 2-bit class byte -> merge 4 lanes into one word
        unsigned cb = (unsigned)(v.x & 3) | ((unsigned)(v.y & 3) << 2)
                    | ((unsigned)(v.z & 3) << 4) | ((unsigned)(v.w & 3) << 6);
        unsigned cw = cb << ((vecIdx & 3) * 8);
        cw |= __shfl_xor_sync(0xffffffffu, cw, 1);
        cw |= __shfl_xor_sync(0xffffffffu, cw, 2);
        const unsigned ci = (unsigned)(vecIdx - HALO / 4);
        if ((lane & 3) == 0 && ci < (unsigned)(CHUNK / 4))
            sCls2[ci >> 2] = cw;
    }
    __syncthreads();

    // ---- Closed-form +-100 window mask per word (WIN=100 > 3*32).
    int cm0 = 0, hp0 = 0;
    {
        const unsigned* P = sPos + GUARD;
        for (int k = tid; k < EXTW; k += TPB) {
            unsigned any5 = P[k-2] | P[k-1] | P[k] | P[k+1] | P[k+2];
            unsigned F    = any5 ? 0xffffffffu : 0u;

            unsigned u3 = P[k+3];
            u3 |= u3 << 1;  u3 |= u3 << 2;  u3 |= u3 << 4;
            u3 |= u3 << 8;  u3 |= u3 << 16; u3 |= u3 >> 4;

            unsigned d3 = P[k-3];
            d3 |= d3 >> 1;  d3 |= d3 >> 2;  d3 |= d3 >> 4;
            d3 |= d3 >> 8;  d3 |= d3 >> 16; d3 |= d3 << 4;

            unsigned n4 = P[k+4] & 0xFu;
            n4 |= n4 << 1; n4 |= n4 << 2;
            unsigned r4 = n4 << 28;

            unsigned h4 = P[k-4] >> 28;
            h4 |= h4 >> 1; h4 |= h4 >> 2;

            unsigned M = F | u3 | d3 | r4 | h4;
            sMsk[GUARD + k] = M;
            if ((unsigned)(k - HALO / 32) < (unsigned)(CHUNK / 32)) {
                cm0 += __popc(M);
                hp0 |= (P[k] != 0u);
            }
        }
    }
    __syncthreads();
    const unsigned* MW = sMsk + GUARD + HALO / 32;

    // ---- Main loop: cp.async 2-stage pipeline, conflict-free LDS.128 consume.
    const float LN2 = 0.69314718055994531f;
    const float a0 = __ldg(alpha + 0) * LN2, a1 = __ldg(alpha + 1) * LN2,
                a2 = __ldg(alpha + 2) * LN2;

    float sm = 0.f, sa = 0.f;

    #pragma unroll 1
    for (int s = 0; s < GRP; s++) {
        asm volatile("cp.async.wait_group 1;" ::: "memory");
        __syncthreads();                              // stage s visible to all

        const float4* sp = &sStage[s & 1][tid * 3];
        float4 A = sp[0];
        float4 B = sp[1];
        float4 C = sp[2];
        __syncthreads();                              // all reads done before refill

        if (s + 2 < GRP) {                            // refill this buffer
            const unsigned dst = (s & 1) ? sb1 : sb0;
            const float4* src = in4 + (size_t)(s + 2) * TPB * 3 + tid * 3;
            cp16(dst,      src);
            cp16(dst + 16, src + 1);
            cp16(dst + 32, src + 2);
        }
        asm volatile("cp.async.commit_group;" ::: "memory");   // one group per iter

        const int g = s * TPB + tid;                  // group index
        const unsigned tv = sCls2[g >> 2] >> ((g & 3) * 8);    // 4 classes, 2b each
        const unsigned mk = MW[g >> 3] >> ((g & 7) * 4);       // 4 mask bits

        elem(A.x, A.y, A.z, (int)( tv       & 3u),  mk       & 1u, a0, a1, a2, sa, sm);
        elem(A.w, B.x, B.y, (int)((tv >> 2) & 3u), (mk >> 1) & 1u, a0, a1, a2, sa, sm);
        elem(B.z, B.w, C.x, (int)((tv >> 4) & 3u), (mk >> 2) & 1u, a0, a1, a2, sa, sm);
        elem(C.y, C.z, C.w, (int)((tv >> 6) & 3u), (mk >> 3) & 1u, a0, a1, a2, sa, sm);
    }

    // ---- Deterministic block reduction, one float4 store per block.
    int cm = cm0, hp = hp0;
    #pragma unroll
    for (int o = 16; o > 0; o >>= 1) {
        sm += __shfl_down_sync(0xffffffffu, sm, o);
        sa += __shfl_down_sync(0xffffffffu, sa, o);
        cm += __shfl_down_sync(0xffffffffu, cm, o);
        hp |= __shfl_down_sync(0xffffffffu, hp, o);
    }
    if (lane == 0) { rA[warp] = sm; rB[warp] = sa; rC[warp] = (float)cm; rH[warp] = hp; }
    __syncthreads();
    if (tid == 0) {
        float Am = 0.f, Bs = 0.f, Cc = 0.f; int H = 0;
        #pragma unroll
        for (int w = 0; w < TPB / 32; w++) { Am += rA[w]; Bs += rB[w]; Cc += rC[w]; H |= rH[w]; }
        g_part[row * CPR + chunk] = make_float4(Am, Bs, Cc, (float)H);
        __threadfence();
        unsigned old = atomicAdd(&g_done, 1u);
        sLast = (old == NBLK - 1);
    }
    __syncthreads();

    // ---- Last block finalizes (result independent of which block runs this).
    if (sLast) {
        __threadfence();
        if (tid < Bq) {
            float psm = 0.f, psa = 0.f, pcm = 0.f; int php = 0;
            #pragma unroll
            for (int k = 0; k < CPR; k++) {
                float4 p = __ldcg(&g_part[tid * CPR + k]);
                psm += p.x; psa += p.y; pcm += p.z; php |= (p.w != 0.f);
            }
            sRS[tid] = php ? psm : psa;
            sRC[tid] = php ? pcm : (float)Sq;
        }
        __syncthreads();
        if (tid == 0) {
            float ts = 0.f, tc = 0.f;
            #pragma unroll
            for (int i = 0; i < Bq; i++) { ts += sRS[i]; tc += sRC[i]; }
            out[0] = ts / tc;
            g_done = 0;   // reset for next graph replay
        }
    }
}

extern "C" void kernel_launch(void* const* d_in, const int* in_sizes, int n_in,
                              void* d_out, int out_size)
{
    const float* inputs  = (const float*)d_in[0];
    const int*   targets = (const int*)d_in[1];
    const float* alpha   = (const float*)d_in[2];

    dim3 grid(CPR, Bq);
    focal_main<<<grid, TPB>>>(inputs, targets, alpha, (float*)d_out);
}

// round 11
// speedup vs baseline: 1.3498x; 1.3498x over previous
#include <cuda_runtime.h>
#include <cuda_bf16.h>

// Problem constants (fixed by the dataset reference)
#define Bq   64
#define Sq   131072
#define SqV  (Sq / 4)
#define WIN  100

#define CHUNK 4096
#define HALO  128                 // halo elements each side (multiple of 32)
#define EXT   (CHUNK + 2*HALO)    // 4608
#define TPB   128
#define CPR   (Sq / CHUNK)        // 32 chunks per row
#define NBLK  (Bq * CPR)          // 2048 blocks < 148*16 -> entire grid resident
#define GRP   (CHUNK / 4 / TPB)   // 8 vector-groups of 4 elements per thread

#define EXTW  (EXT / 32)          // 144 bitmap words
#define EXTV  (EXT / 4)           // 1152 int4 target vectors
#define GUARD 4                   // zero guard words each side (formula reads k+-4)
#define PADW  (EXTW + 2*GUARD)    // 152

// Per-(row,chunk) partials: x=sum_masked, y=sum_all, z=count_masked, w=has_pos.
__device__ float4       g_part[NBLK];
__device__ unsigned int g_done;   // zero at start; last block resets -> replay safe

__device__ __forceinline__ float fex2(float x) {
    float r; asm("ex2.approx.ftz.f32 %0, %1;" : "=f"(r) : "f"(x)); return r;
}
__device__ __forceinline__ float flg2(float x) {
    float r; asm("lg2.approx.ftz.f32 %0, %1;" : "=f"(r) : "f"(x)); return r;
}
__device__ __forceinline__ float frcp(float x) {
    float r; asm("rcp.approx.ftz.f32 %0, %1;" : "=f"(r) : "f"(x)); return r;
}

// One element: x0..x2 logits, t class, m mask bit (0/1). aw pre-scaled by ln2.
__device__ __forceinline__ void elem(float x0, float x1, float x2,
                                     int t, unsigned m,
                                     float a0, float a1, float a2,
                                     float& sa, float& sm)
{
    const float L2E = 1.44269504088896340736f;
    float xt  = (t == 0) ? x0 : ((t == 1) ? x1 : x2);
    float xa  = (t == 0) ? x1 : x0;
    float xb  = (t <  2) ? x2 : x1;
    float aw  = (t == 0) ? a0 : ((t == 1) ? a1 : a2);
    float nxt = -xt * L2E;
    float ea  = fex2(__fmaf_rn(xa, L2E, nxt));
    float eb  = fex2(__fmaf_rn(xb, L2E, nxt));
    float q   = 1.f + ea + eb;            // = softmax_sum / e_t
    float ce2 = flg2(q);                  // ln2 folded into aw
    float p   = frcp(q);                  // p_t
    float omp = 1.f - p;
    float f   = aw * (omp * omp) * ce2;
    sa += f;
    if (m) sm += f;
}

__global__ __launch_bounds__(TPB, 16)  // 32 regs -> 16 CTAs/SM -> whole grid resident
void focal_main(const float* __restrict__ inputs,
                const int*   __restrict__ targets,
                const float* __restrict__ alpha,
                float*       __restrict__ out)
{
    __shared__ unsigned sPos[PADW];        // positive-flag bitmap (+guards)
    __shared__ unsigned sMsk[PADW];        // window-mask bitmap
    __shared__ unsigned sClsW[CHUNK / 4];  // packed class bytes (chunk interior)
    __shared__ float rA[TPB / 32], rB[TPB / 32], rC[TPB / 32];
    __shared__ int   rH[TPB / 32];
    __shared__ float sRS[Bq], sRC[Bq];
    __shared__ bool  sLast;

    const int row        = blockIdx.y;
    const int chunk      = blockIdx.x;
    const int chunkStart = chunk * CHUNK;
    const int tid        = threadIdx.x;
    const int lane       = tid & 31, warp = tid >> 5;

    // ---- Zero bitmap guards.
    if (tid < GUARD) { sPos[tid] = 0; sPos[PADW - 1 - tid] = 0; }

    // ---- Vectorized target load: int4 -> flag nibble -> word via 3x shfl_xor.
    const int4* tgt4     = reinterpret_cast<const int4*>(targets);
    const int   rowVecLo = row * SqV;
    const int   baseVec  = rowVecLo + (chunkStart - HALO) / 4;

    #pragma unroll 1
    for (int it = 0; it < 9; it++) {                 // 9*128 covers 1152 vectors
        const int vecIdx = it * TPB + tid;
        const int gv     = baseVec + vecIdx;
        const int gvc    = min(max(gv, rowVecLo), rowVecLo + SqV - 1);
        int4 v = __ldg(tgt4 + gvc);
        const bool valid = (unsigned)(gv - rowVecLo) < (unsigned)SqV;

        unsigned nib = (v.x > 0 ? 1u : 0u) | (v.y > 0 ? 2u : 0u)
                     | (v.z > 0 ? 4u : 0u) | (v.w > 0 ? 8u : 0u);
        if (!valid) nib = 0;

        unsigned wv = nib << ((lane & 7) * 4);       // 8 lanes build one word
        wv |= __shfl_xor_sync(0xffffffffu, wv, 1);
        wv |= __shfl_xor_sync(0xffffffffu, wv, 2);
        wv |= __shfl_xor_sync(0xffffffffu, wv, 4);
        if ((lane & 7) == 0) sPos[GUARD + (vecIdx >> 3)] = wv;

        const unsigned ci = (unsigned)(vecIdx - HALO / 4);
        if (ci < (unsigned)(CHUNK / 4))
            sClsW[ci] = (unsigned)(v.x & 3) | ((unsigned)(v.y & 3) << 8)
                      | ((unsigned)(v.z & 3) << 16) | ((unsigned)(v.w & 3) << 24);
    }
    __syncthreads();

    // ---- Closed-form +-100 window mask per word (WIN=100 > 3*32).
    int cm0 = 0, hp0 = 0;
    {
        const unsigned* P = sPos + GUARD;
        #pragma unroll 1
        for (int k = tid; k < EXTW; k += TPB) {
            unsigned any5 = P[k-2] | P[k-1] | P[k] | P[k+1] | P[k+2];
            unsigned F    = any5 ? 0xffffffffu : 0u;

            unsigned u3 = P[k+3];                    // covers bits i >= b-4
            u3 |= u3 << 1;  u3 |= u3 << 2;  u3 |= u3 << 4;
            u3 |= u3 << 8;  u3 |= u3 << 16; u3 |= u3 >> 4;

            unsigned d3 = P[k-3];                    // covers bits i <= b+4
            d3 |= d3 >> 1;  d3 |= d3 >> 2;  d3 |= d3 >> 4;
            d3 |= d3 >> 8;  d3 |= d3 >> 16; d3 |= d3 << 4;

            unsigned n4 = P[k+4] & 0xFu;             // covers bits i >= b+28
            n4 |= n4 << 1; n4 |= n4 << 2;
            unsigned r4 = n4 << 28;

            unsigned h4 = P[k-4] >> 28;              // covers bits i <= b-28
            h4 |= h4 >> 1; h4 |= h4 >> 2;

            unsigned M = F | u3 | d3 | r4 | h4;
            sMsk[GUARD + k] = M;
            if ((unsigned)(k - HALO / 32) < (unsigned)(CHUNK / 32)) {
                cm0 += __popc(M);
                hp0 |= (P[k] != 0u);
            }
        }
    }
    __syncthreads();
    const unsigned* MW = sMsk + GUARD + HALO / 32;

    // ---- Main compute: 4 elements/group, 3x LDG.128, spill-free (R8 structure).
    const float LN2 = 0.69314718055994531f;
    const float a0 = __ldg(alpha + 0) * LN2, a1 = __ldg(alpha + 1) * LN2,
                a2 = __ldg(alpha + 2) * LN2;
    const float4* in4 = reinterpret_cast<const float4*>(
        inputs + ((size_t)row * Sq + (size_t)chunkStart) * 3);

    float sm = 0.f, sa = 0.f;

    #pragma unroll 1
    for (int k = 0; k < GRP; k++) {
        const int g = k * TPB + tid;                 // elements [4g, 4g+4)
        const unsigned tv = sClsW[g];
        const unsigned mk = MW[g >> 3] >> ((g & 7) * 4);
        float4 A = __ldcs(in4 + 3 * g + 0);
        float4 B = __ldcs(in4 + 3 * g + 1);
        float4 C = __ldcs(in4 + 3 * g + 2);

        elem(A.x, A.y, A.z, (int)( tv        & 3u), mk        & 1u, a0, a1, a2, sa, sm);
        elem(A.w, B.x, B.y, (int)((tv >>  8) & 3u), (mk >> 1) & 1u, a0, a1, a2, sa, sm);
        elem(B.z, B.w, C.x, (int)((tv >> 16) & 3u), (mk >> 2) & 1u, a0, a1, a2, sa, sm);
        elem(C.y, C.z, C.w, (int)((tv >> 24) & 3u), (mk >> 3) & 1u, a0, a1, a2, sa, sm);
    }

    // ---- Deterministic block reduction, one float4 store per block.
    int cm = cm0, hp = hp0;
    #pragma unroll
    for (int o = 16; o > 0; o >>= 1) {
        sm += __shfl_down_sync(0xffffffffu, sm, o);
        sa += __shfl_down_sync(0xffffffffu, sa, o);
        cm += __shfl_down_sync(0xffffffffu, cm, o);
        hp |= __shfl_down_sync(0xffffffffu, hp, o);
    }
    if (lane == 0) { rA[warp] = sm; rB[warp] = sa; rC[warp] = (float)cm; rH[warp] = hp; }
    __syncthreads();
    if (tid == 0) {
        float Am = 0.f, Bs = 0.f, Cc = 0.f; int H = 0;
        #pragma unroll
        for (int w = 0; w < TPB / 32; w++) { Am += rA[w]; Bs += rB[w]; Cc += rC[w]; H |= rH[w]; }
        g_part[row * CPR + chunk] = make_float4(Am, Bs, Cc, (float)H);
        __threadfence();
        unsigned old = atomicAdd(&g_done, 1u);
        sLast = (old == NBLK - 1);
    }
    __syncthreads();

    // ---- Last block finalizes (result independent of which block runs this).
    if (sLast) {
        __threadfence();
        if (tid < Bq) {
            float psm = 0.f, psa = 0.f, pcm = 0.f; int php = 0;
            #pragma unroll 4
            for (int k = 0; k < CPR; k++) {
                float4 p = __ldcg(&g_part[tid * CPR + k]);
                psm += p.x; psa += p.y; pcm += p.z; php |= (p.w != 0.f);
            }
            sRS[tid] = php ? psm : psa;
            sRC[tid] = php ? pcm : (float)Sq;
        }
        __syncthreads();
        if (tid == 0) {
            float ts = 0.f, tc = 0.f;
            #pragma unroll
            for (int i = 0; i < Bq; i++) { ts += sRS[i]; tc += sRC[i]; }
            out[0] = ts / tc;
            g_done = 0;   // reset for next graph replay
        }
    }
}

extern "C" void kernel_launch(void* const* d_in, const int* in_sizes, int n_in,
                              void* d_out, int out_size)
{
    const float* inputs  = (const float*)d_in[0];
    const int*   targets = (const int*)d_in[1];
    const float* alpha   = (const float*)d_in[2];

    dim3 grid(CPR, Bq);
    focal_main<<<grid, TPB>>>(inputs, targets, alpha, (float*)d_out);
}